// round 6
// baseline (speedup 1.0000x reference)
#include <cuda_runtime.h>
#include <cstdint>

__device__ __forceinline__ float rcp_approx_(float x) {
    float r;
    asm("rcp.approx.f32 %0, %1;" : "=f"(r) : "f"(x));
    return r;
}

#define GMF_D 0.16666667163372039794921875  /* fp32(1/6) = 0x3E2AAAAB, as double */
#define VPT 8   /* float4 per thread */

// Core: one float4 (quarter of a 16-elem group). Lane quads own whole groups.
__device__ __forceinline__ float4 quant_f4_(float4 v) {
    const float C   = (float)(1.0 / (6.0 * GMF_D));   // RN(1/(6*gm))
    const float GMH = (float)(GMF_D * 0.5);           // gm/2, exact halving

    // Group amax: per-thread partial + 2-level butterfly over the lane quad.
    float ax = fmaxf(fmaxf(fabsf(v.x), fabsf(v.y)),
                     fmaxf(fabsf(v.z), fabsf(v.w)));
    ax = fmaxf(ax, __shfl_xor_sync(0xFFFFFFFFu, ax, 1));
    ax = fmaxf(ax, __shfl_xor_sync(0xFFFFFFFFu, ax, 2));

    // sraw = (amax/gm)/6 ~= amax * C (<=1 ulp).
    float sraw = ax * C;

    // e4m3 rounding: keep top-3 mantissa bits, round-half-DOWN
    // ((low20 > 0x80000) <=> (low20 + 0x7FFFF) carries), clamp [2^-7, 480].
    unsigned res = (__float_as_uint(sraw) + 0x7FFFFu) & 0xFFF00000u;
    res = max(res, 0x3C000000u);   // 2^-7
    res = min(res, 0x43F00000u);   // 480
    float scale = __uint_as_float(res);

    // Doubled domain: u' = 2 * x/(gm*scale) = x * (12*rcp(scale)).
    // RN commutes with *2, so u' == 2u exactly; thresholds double exactly.
    float R2  = 12.0f * rcp_approx_(scale);
    float sg2 = scale * GMH;   // out = q' * (scale*gm/2), q' = doubled bucket

    float xs[4] = {v.x, v.y, v.z, v.w};
    float ys[4];
#pragma unroll
    for (int i = 0; i < 4; i++) {
        float u = xs[i] * R2;
        float a = fabsf(u);

        // Bit-round valid only where doubled-E2M1 == 1-mantissa-bit grid:
        // binades [2,4)={2,3}, [4,8)={4,6}, [8,16)={8,12}. Clamp to [2,12].
        float a2 = fminf(fmaxf(a, 2.0f), 12.0f);
        unsigned qb = (__float_as_uint(a2) + 0x00201000u) & 0xFFC00000u;
        float q = __uint_as_float(qb);

        // Linear low buckets {0,1,2}: doubled thresholds (exact binary).
        q = (a >= 1.49951171875f)   ? q : 1.0f;
        q = (a >= 0.4998779296875f) ? q : 0.0f;

        // Sign from u (one LOP3), then single output multiply.
        float qs = __uint_as_float(__float_as_uint(q) |
                                   (__float_as_uint(u) & 0x80000000u));
        ys[i] = qs * sg2;
    }
    return make_float4(ys[0], ys[1], ys[2], ys[3]);
}

__global__ __launch_bounds__(256)
void actquant_nvfp4_kernel(const float4* __restrict__ in,
                           float4* __restrict__ out,
                           int nvec) {
    const int t = blockIdx.x * blockDim.x + threadIdx.x;
    const int S = gridDim.x * blockDim.x;

    if (t + (VPT - 1) * S < nvec) {
        // Fast path: 8 front-batched coalesced LDG.128 (MLP_p1 = 8).
        float4 v[VPT];
#pragma unroll
        for (int k = 0; k < VPT; k++) v[k] = in[t + k * S];
#pragma unroll
        for (int k = 0; k < VPT; k++) out[t + k * S] = quant_f4_(v[k]);
    } else {
#pragma unroll
        for (int k = 0; k < VPT; k++) {
            int idx = t + k * S;
            // Whole lane quads pass/fail together (S and nvec are multiples
            // of 4 since GROUP=16), so shuffles inside see live partners.
            if (idx < nvec) out[idx] = quant_f4_(in[idx]);
        }
    }
}

extern "C" void kernel_launch(void* const* d_in, const int* in_sizes, int n_in,
                              void* d_out, int out_size) {
    const float4* in  = (const float4*)d_in[0];
    float4*       out = (float4*)d_out;
    int n = in_sizes[0];
    int nvec = n / 4;               // one float4 = quarter group
    int threads = 256;
    int blocks = (nvec + threads * VPT - 1) / (threads * VPT);
    actquant_nvfp4_kernel<<<blocks, threads>>>(in, out, nvec);
}